// round 8
// baseline (speedup 1.0000x reference)
#include <cuda_runtime.h>
#include <math.h>
#include <stdint.h>

#define NN 10000
#define EE 320000
#define FF 128
#define HH 128
#define TT 16
#define OO 128

// ---------------- static device scratch ----------------
__device__ float g_xT[TT * NN * FF];      // (T,N,F) transposed input
__device__ float g_hseq[NN * TT * HH];    // (N,T,H) top-layer states
__device__ float g_h0[NN * HH];
__device__ float g_h1[NN * HH];
__device__ float g_zg[NN * HH];           // sigmoid(z), round-trips through L2 within a layer step
__device__ float g_ctx[NN * HH];
__device__ int   g_rowptr[NN + 1];
__device__ int   g_count[NN];
__device__ float g_degsum[NN];
__device__ int   g_cursor[NN];
__device__ int   g_cols[EE];
__device__ float g_vals[EE];
__device__ float g_dinv[NN];
__device__ float g_selfn[NN];
// Fused gate weights pre-split to tf32 hi/lo. Layout [k=256][n], k<128 = agg rows, k>=128 = hp rows.
__device__ uint32_t g_WzrH[2 * 256 * 256];
__device__ uint32_t g_WzrL[2 * 256 * 256];
__device__ uint32_t g_WhH[2 * 256 * 128];
__device__ uint32_t g_WhL[2 * 256 * 128];
__device__ float g_bzr[2 * 256];
__device__ float g_bh[2 * 128];

struct WPtrs {
    const float* Wc[3];
    const float* bc[3];
    const float* Wl[3];
    const float* bl[3];
};

// ---------------- tf32 helpers ----------------
__device__ __forceinline__ uint32_t f2tf(float x) {
    uint32_t r;
    asm("cvt.rna.tf32.f32 %0, %1;" : "=r"(r) : "f"(x));
    return r;
}

__device__ __forceinline__ void mma_tf32(float* c, const uint32_t* a, const uint32_t* b) {
    asm volatile(
        "mma.sync.aligned.m16n8k8.row.col.f32.tf32.tf32.f32 "
        "{%0,%1,%2,%3}, {%4,%5,%6,%7}, {%8,%9}, {%0,%1,%2,%3};\n"
        : "+f"(c[0]), "+f"(c[1]), "+f"(c[2]), "+f"(c[3])
        : "r"(a[0]), "r"(a[1]), "r"(a[2]), "r"(a[3]), "r"(b[0]), "r"(b[1]));
}

// ---------------- preprocessing ----------------

// Fused weights -> tf32 hi/lo: W_top = Wc @ Wl_top, W_bot = Wl_bot, bias = bc @ Wl_top + bl.
// Also zeroes the edge counters.
__global__ void k_prep(WPtrs P) {
    int flat = (blockIdx.y * gridDim.x + blockIdx.x) * blockDim.x + threadIdx.x;
    if (flat < NN) { g_count[flat] = 0; g_degsum[flat] = 0.f; }

    int lg = blockIdx.y;                // 0..5
    int l = lg / 3, g = lg % 3;
    int i = blockIdx.x;                 // row 0..127
    int j = threadIdx.x;                // col 0..127
    const float* Wc = P.Wc[g] + l * HH * HH;
    const float* Wl = P.Wl[g] + l * 2 * HH * HH;
    float c = 0.f;
    for (int k = 0; k < HH; k++) c += Wc[i * HH + k] * Wl[k * HH + j];
    float bot = Wl[(HH + i) * HH + j];
    uint32_t cH = f2tf(c),   cL = f2tf(c - __uint_as_float(cH));
    uint32_t bH = f2tf(bot), bL = f2tf(bot - __uint_as_float(bH));
    if (g < 2) {
        size_t topi = (size_t)l * 256 * 256 + i * 256 + g * HH + j;
        size_t boti = (size_t)l * 256 * 256 + (HH + i) * 256 + g * HH + j;
        g_WzrH[topi] = cH; g_WzrL[topi] = cL;
        g_WzrH[boti] = bH; g_WzrL[boti] = bL;
    } else {
        size_t topi = (size_t)l * 256 * 128 + i * 128 + j;
        size_t boti = (size_t)l * 256 * 128 + (HH + i) * 128 + j;
        g_WhH[topi] = cH; g_WhL[topi] = cL;
        g_WhH[boti] = bH; g_WhL[boti] = bL;
    }
    if (i == 0) {
        const float* bc = P.bc[g] + l * HH;
        const float* bl = P.bl[g] + l * HH;
        float b = 0.f;
        for (int k = 0; k < HH; k++) b += bc[k] * Wl[k * HH + j];
        b += bl[j];
        if (g < 2) g_bzr[l * 256 + g * HH + j] = b;
        else       g_bh[l * 128 + j] = b;
    }
}

// Transpose x (N,F,T)->(T,N,F), zero states, and count edges per dst.
__global__ void k_init(const float* __restrict__ x,
                       const int* __restrict__ ei, const float* __restrict__ ew) {
    int idx = blockIdx.x * blockDim.x + threadIdx.x;   // over N*F
    if (idx >= NN * FF) return;
    const float4* xr = (const float4*)(x + (size_t)idx * TT);
    float v[16];
    float4 q;
    q = xr[0]; v[0]=q.x; v[1]=q.y; v[2]=q.z; v[3]=q.w;
    q = xr[1]; v[4]=q.x; v[5]=q.y; v[6]=q.z; v[7]=q.w;
    q = xr[2]; v[8]=q.x; v[9]=q.y; v[10]=q.z; v[11]=q.w;
    q = xr[3]; v[12]=q.x; v[13]=q.y; v[14]=q.z; v[15]=q.w;
#pragma unroll
    for (int t = 0; t < TT; t++)
        g_xT[t * (NN * FF) + idx] = v[t];
    g_h0[idx] = 0.f;
    g_h1[idx] = 0.f;
    if (idx < EE) {
        int d = ei[EE + idx];
        atomicAdd(&g_count[d], 1);
        atomicAdd(&g_degsum[d], ew[idx]);
    }
}

__global__ void k_scan() {
    __shared__ int sdata[1024];
    __shared__ int s_off;
    int tid = threadIdx.x;
    for (int i = tid; i < NN; i += 1024) {
        float dinv = rsqrtf(g_degsum[i] + 1.0f);
        g_dinv[i] = dinv;
        g_selfn[i] = dinv * dinv;
    }
    if (tid == 0) s_off = 0;
    __syncthreads();
    for (int base = 0; base < NN; base += 1024) {
        int v = (base + tid < NN) ? g_count[base + tid] : 0;
        sdata[tid] = v;
        __syncthreads();
        for (int d = 1; d < 1024; d <<= 1) {
            int t2 = (tid >= d) ? sdata[tid - d] : 0;
            __syncthreads();
            sdata[tid] += t2;
            __syncthreads();
        }
        int excl = sdata[tid] - v;
        if (base + tid < NN) {
            g_rowptr[base + tid] = s_off + excl;
            g_cursor[base + tid] = s_off + excl;
        }
        __syncthreads();
        int chunk_total = sdata[1023];
        if (tid == 0) s_off += chunk_total;
        __syncthreads();
    }
    if (tid == 0) g_rowptr[NN] = s_off;
}

__global__ void k_scatter(const int* __restrict__ ei, const float* __restrict__ ew) {
    int e = blockIdx.x * blockDim.x + threadIdx.x;
    if (e >= EE) return;
    int s = ei[e], d = ei[EE + e];
    int p = atomicAdd(&g_cursor[d], 1);
    g_cols[p] = s;
    g_vals[p] = ew[e] * g_dinv[s] * g_dinv[d];
}

// ---------------- fused layer-step kernel ----------------
// One block = 64 node-rows. Phases (all block-local):
//   0) SpMM for my rows -> sA (fp32); load hp -> sA2 (fp32)
//   1) gate GEMM [sA|sA2] @ Wzr(256x256): z -> g_zg (global), r*hp -> sA2 (in place)
//   2) cand GEMM [sA|sA2] @ Wh(256x128): h = z*hp + (1-z)*tanh; write hstate (+hseq)
// Weights arrive pre-split tf32 hi/lo; A converted to hi/lo inline at fragment load.

#define SA 132                          // A smem row stride (floats)

template<int NT>   // NT = warp n8-tiles; N = NT*32 total (warp layout 2m x 4n)
__device__ __forceinline__ void gemm_phase(
    const float* sA, const float* sA2, uint32_t* sBh, uint32_t* sBl,
    const uint32_t* __restrict__ Bh, const uint32_t* __restrict__ Bl, int ldb,
    int tid, int lane, int warp_m, int warp_n, float (&acc)[2][NT][4]) {
    constexpr int NB = NT * 32;
    constexpr int SB = NB + 8;
#pragma unroll
    for (int i = 0; i < 2; i++)
#pragma unroll
        for (int j = 0; j < NT; j++)
#pragma unroll
            for (int q = 0; q < 4; q++) acc[i][j][q] = 0.f;

    for (int kt = 0; kt < 256; kt += 16) {
        for (int i = tid * 4; i < 16 * NB; i += 1024) {
            int k = i / NB, n = i % NB;
            *(uint4*)&sBh[k * SB + n] = *(const uint4*)&Bh[(size_t)(kt + k) * ldb + n];
            *(uint4*)&sBl[k * SB + n] = *(const uint4*)&Bl[(size_t)(kt + k) * ldb + n];
        }
        __syncthreads();
        const float* Asrc = (kt < 128) ? sA : sA2;
        const int colb = (kt & 127) + (lane & 3);
#pragma unroll
        for (int k0 = 0; k0 < 16; k0 += 8) {
            uint32_t ah[2][4], al[2][4];
#pragma unroll
            for (int mt = 0; mt < 2; mt++) {
                int ar = (warp_m * 32 + mt * 16 + (lane >> 2)) * SA + colb + k0;
                float a0 = Asrc[ar],            a1 = Asrc[ar + 8 * SA];
                float a2 = Asrc[ar + 4],        a3 = Asrc[ar + 8 * SA + 4];
                ah[mt][0] = f2tf(a0); al[mt][0] = f2tf(a0 - __uint_as_float(ah[mt][0]));
                ah[mt][1] = f2tf(a1); al[mt][1] = f2tf(a1 - __uint_as_float(ah[mt][1]));
                ah[mt][2] = f2tf(a2); al[mt][2] = f2tf(a2 - __uint_as_float(ah[mt][2]));
                ah[mt][3] = f2tf(a3); al[mt][3] = f2tf(a3 - __uint_as_float(ah[mt][3]));
            }
#pragma unroll
            for (int nt = 0; nt < NT; nt++) {
                int ncol = warp_n * (NT * 8) + nt * 8 + (lane >> 2);
                int kr = (k0 + (lane & 3)) * SB;
                uint32_t bh[2], bl[2];
                bh[0] = sBh[kr + ncol]; bh[1] = sBh[kr + 4 * SB + ncol];
                bl[0] = sBl[kr + ncol]; bl[1] = sBl[kr + 4 * SB + ncol];
#pragma unroll
                for (int mt = 0; mt < 2; mt++) {
                    mma_tf32(acc[mt][nt], ah[mt], bh);
                    mma_tf32(acc[mt][nt], ah[mt], bl);
                    mma_tf32(acc[mt][nt], al[mt], bh);
                }
            }
        }
        __syncthreads();
    }
}

template<int WSEQ>
__global__ void __launch_bounds__(256)
k_layer(const float* __restrict__ in, float* __restrict__ hstate,
        const uint32_t* __restrict__ WzrH, const uint32_t* __restrict__ WzrL,
        const float* __restrict__ bzr,
        const uint32_t* __restrict__ WhH, const uint32_t* __restrict__ WhL,
        const float* __restrict__ bh, int t) {
    extern __shared__ float smem[];
    float* sA  = smem;                       // 64 x SA (agg)
    float* sA2 = smem + 64 * SA;             // 64 x SA (hp -> r*hp)
    uint32_t* sBh = (uint32_t*)(smem + 2 * 64 * SA);
    uint32_t* sBl = sBh + 16 * 264;

    const int tid = threadIdx.x;
    const int lane = tid & 31;
    const int wid = tid >> 5;
    const int warp_m = wid & 1;
    const int warp_n = wid >> 1;
    const int row0 = blockIdx.x * 64;

    // ---- phase 0: hp load + SpMM ----
    for (int i = tid; i < 64 * 32; i += 256) {
        int r = i >> 5, c4 = i & 31;
        int grow = row0 + r;
        float4 v = (grow < NN) ? ((const float4*)hstate)[grow * 32 + c4]
                               : make_float4(0.f, 0.f, 0.f, 0.f);
        *(float4*)&sA2[r * SA + c4 * 4] = v;
    }
    {
        const float4* in4 = (const float4*)in;
        for (int r = wid; r < 64; r += 8) {
            int grow = row0 + r;
            float ax = 0.f, ay = 0.f, az = 0.f, aw = 0.f;
            float bx = 0.f, by = 0.f, bz = 0.f, bw = 0.f;
            if (grow < NN) {
                float sn = g_selfn[grow];
                float4 hv = in4[grow * 32 + lane];
                ax = sn * hv.x; ay = sn * hv.y; az = sn * hv.z; aw = sn * hv.w;
                int p = g_rowptr[grow], pe = g_rowptr[grow + 1];
                for (; p + 1 < pe; p += 2) {
                    float v0 = g_vals[p],     v1 = g_vals[p + 1];
                    int   c0 = g_cols[p],     c1 = g_cols[p + 1];
                    float4 b0 = in4[c0 * 32 + lane];
                    float4 b1 = in4[c1 * 32 + lane];
                    ax += v0 * b0.x; ay += v0 * b0.y; az += v0 * b0.z; aw += v0 * b0.w;
                    bx += v1 * b1.x; by += v1 * b1.y; bz += v1 * b1.z; bw += v1 * b1.w;
                }
                if (p < pe) {
                    float v0 = g_vals[p]; int c0 = g_cols[p];
                    float4 b0 = in4[c0 * 32 + lane];
                    ax += v0 * b0.x; ay += v0 * b0.y; az += v0 * b0.z; aw += v0 * b0.w;
                }
            }
            *(float4*)&sA[r * SA + lane * 4] =
                make_float4(ax + bx, ay + by, az + bz, aw + bw);
        }
    }
    __syncthreads();

    // ---- phase 1: gate GEMM (N=256) ----
    {
        float acc[2][8][4];
        gemm_phase<8>(sA, sA2, sBh, sBl, WzrH, WzrL, 256,
                      tid, lane, warp_m, warp_n, acc);
        // epilogue: sigmoid; z -> g_zg, r*hp -> sA2 (in place, owner-exclusive)
#pragma unroll
        for (int mt = 0; mt < 2; mt++) {
#pragma unroll
            for (int nt = 0; nt < 8; nt++) {
                int gcol = warp_n * 64 + nt * 8 + (lane & 3) * 2;
                float b0 = bzr[gcol], b1 = bzr[gcol + 1];
#pragma unroll
                for (int half = 0; half < 2; half++) {
                    int lr = warp_m * 32 + mt * 16 + (lane >> 2) + half * 8;
                    int grow = row0 + lr;
                    float v0 = acc[mt][nt][half * 2 + 0] + b0;
                    float v1 = acc[mt][nt][half * 2 + 1] + b1;
                    v0 = 1.f / (1.f + expf(-v0));
                    v1 = 1.f / (1.f + expf(-v1));
                    if (gcol < 128) {
                        if (grow < NN)
                            *(float2*)&g_zg[(size_t)grow * 128 + gcol] = make_float2(v0, v1);
                    } else {
                        int lc = gcol - 128;
                        float hp0 = sA2[lr * SA + lc];
                        float hp1 = sA2[lr * SA + lc + 1];
                        sA2[lr * SA + lc]     = v0 * hp0;
                        sA2[lr * SA + lc + 1] = v1 * hp1;
                    }
                }
            }
        }
    }
    // (next phase's first __syncthreads orders the sA2 writes before reads)

    // ---- phase 2: candidate GEMM (N=128) + blend ----
    {
        float acc[2][4][4];
        gemm_phase<4>(sA, sA2, sBh, sBl, WhH, WhL, 128,
                      tid, lane, warp_m, warp_n, acc);
#pragma unroll
        for (int mt = 0; mt < 2; mt++) {
#pragma unroll
            for (int nt = 0; nt < 4; nt++) {
                int gcol = warp_n * 32 + nt * 8 + (lane & 3) * 2;
                float b0 = bh[gcol], b1 = bh[gcol + 1];
#pragma unroll
                for (int half = 0; half < 2; half++) {
                    int lr = warp_m * 32 + mt * 16 + (lane >> 2) + half * 8;
                    int grow = row0 + lr;
                    if (grow >= NN) continue;
                    size_t base = (size_t)grow * 128 + gcol;
                    float v0 = tanhf(acc[mt][nt][half * 2 + 0] + b0);
                    float v1 = tanhf(acc[mt][nt][half * 2 + 1] + b1);
                    float2 zv = *(const float2*)&g_zg[base];
                    float2 hv = *(const float2*)&hstate[base];
                    float hn0 = zv.x * hv.x + (1.f - zv.x) * v0;
                    float hn1 = zv.y * hv.y + (1.f - zv.y) * v1;
                    *(float2*)&hstate[base] = make_float2(hn0, hn1);
                    if (WSEQ) {
                        size_t sb = (size_t)grow * (TT * HH) + t * HH + gcol;
                        *(float2*)&g_hseq[sb] = make_float2(hn0, hn1);
                    }
                }
            }
        }
    }
}

// ---------------- final projection (3xTF32, inline conversion) ----------------
__global__ void __launch_bounds__(256)
k_proj(const float* __restrict__ A1, const float* __restrict__ B,
       const float* __restrict__ bias, float* __restrict__ Cout, int M) {
    constexpr int SAp = 20;
    constexpr int SB = 72;
    __shared__ float sAh[128 * SAp];
    __shared__ float sAl[128 * SAp];
    __shared__ float sBh[16 * SB];
    __shared__ float sBl[16 * SB];

    const int tid = threadIdx.x;
    const int lane = tid & 31;
    const int wid = tid >> 5;
    const int warp_m = wid & 3;
    const int warp_n = wid >> 2;
    const int row0 = blockIdx.x * 128;
    const int col0 = blockIdx.y * 64;

    float acc[2][4][4];
#pragma unroll
    for (int i = 0; i < 2; i++)
#pragma unroll
        for (int j = 0; j < 4; j++)
#pragma unroll
            for (int q = 0; q < 4; q++) acc[i][j][q] = 0.f;

    for (int kt = 0; kt < 128; kt += 16) {
#pragma unroll
        for (int i = 0; i < 2; i++) {
            int lid = tid + i * 256;
            int m = lid >> 2, kq = (lid & 3) * 4;
            int grow = row0 + m;
            float4 a = (grow < M) ? *(const float4*)(A1 + (size_t)grow * 128 + kt + kq)
                                  : make_float4(0.f, 0.f, 0.f, 0.f);
            float4 h4, l4;
            h4.x = __uint_as_float(f2tf(a.x)); l4.x = __uint_as_float(f2tf(a.x - h4.x));
            h4.y = __uint_as_float(f2tf(a.y)); l4.y = __uint_as_float(f2tf(a.y - h4.y));
            h4.z = __uint_as_float(f2tf(a.z)); l4.z = __uint_as_float(f2tf(a.z - h4.z));
            h4.w = __uint_as_float(f2tf(a.w)); l4.w = __uint_as_float(f2tf(a.w - h4.w));
            *(float4*)&sAh[m * SAp + kq] = h4;
            *(float4*)&sAl[m * SAp + kq] = l4;
        }
        {
            int k = tid >> 4, nq = (tid & 15) * 4;
            float4 b = *(const float4*)&B[(size_t)(kt + k) * 128 + col0 + nq];
            float4 h4, l4;
            h4.x = __uint_as_float(f2tf(b.x)); l4.x = __uint_as_float(f2tf(b.x - h4.x));
            h4.y = __uint_as_float(f2tf(b.y)); l4.y = __uint_as_float(f2tf(b.y - h4.y));
            h4.z = __uint_as_float(f2tf(b.z)); l4.z = __uint_as_float(f2tf(b.z - h4.z));
            h4.w = __uint_as_float(f2tf(b.w)); l4.w = __uint_as_float(f2tf(b.w - h4.w));
            *(float4*)&sBh[k * SB + nq] = h4;
            *(float4*)&sBl[k * SB + nq] = l4;
        }
        __syncthreads();
#pragma unroll
        for (int k0 = 0; k0 < 16; k0 += 8) {
            uint32_t ah[2][4], al[2][4];
#pragma unroll
            for (int mt = 0; mt < 2; mt++) {
                int r0 = (warp_m * 32 + mt * 16 + (lane >> 2)) * SAp;
                int c0k = k0 + (lane & 3);
                ah[mt][0] = __float_as_uint(sAh[r0 + c0k]);
                ah[mt][1] = __float_as_uint(sAh[r0 + 8 * SAp + c0k]);
                ah[mt][2] = __float_as_uint(sAh[r0 + c0k + 4]);
                ah[mt][3] = __float_as_uint(sAh[r0 + 8 * SAp + c0k + 4]);
                al[mt][0] = __float_as_uint(sAl[r0 + c0k]);
                al[mt][1] = __float_as_uint(sAl[r0 + 8 * SAp + c0k]);
                al[mt][2] = __float_as_uint(sAl[r0 + c0k + 4]);
                al[mt][3] = __float_as_uint(sAl[r0 + 8 * SAp + c0k + 4]);
            }
#pragma unroll
            for (int nt = 0; nt < 4; nt++) {
                int ncol = warp_n * 32 + nt * 8 + (lane >> 2);
                int kr = (k0 + (lane & 3)) * SB;
                uint32_t bh[2], bl[2];
                bh[0] = __float_as_uint(sBh[kr + ncol]);
                bh[1] = __float_as_uint(sBh[kr + 4 * SB + ncol]);
                bl[0] = __float_as_uint(sBl[kr + ncol]);
                bl[1] = __float_as_uint(sBl[kr + 4 * SB + ncol]);
#pragma unroll
                for (int mt = 0; mt < 2; mt++) {
                    mma_tf32(acc[mt][nt], ah[mt], bh);
                    mma_tf32(acc[mt][nt], ah[mt], bl);
                    mma_tf32(acc[mt][nt], al[mt], bh);
                }
            }
        }
        __syncthreads();
    }
#pragma unroll
    for (int mt = 0; mt < 2; mt++) {
#pragma unroll
        for (int nt = 0; nt < 4; nt++) {
            int gcol = col0 + warp_n * 32 + nt * 8 + (lane & 3) * 2;
            float b0 = bias[gcol], b1 = bias[gcol + 1];
#pragma unroll
            for (int half = 0; half < 2; half++) {
                int row = row0 + warp_m * 32 + mt * 16 + (lane >> 2) + half * 8;
                if (row >= M) continue;
                *(float2*)&Cout[(size_t)row * 128 + gcol] =
                    make_float2(acc[mt][nt][half * 2 + 0] + b0,
                                acc[mt][nt][half * 2 + 1] + b1);
            }
        }
    }
}

// Temporal attention: warp per node (att_b cancels inside softmax).
__global__ void __launch_bounds__(128)
k_attn(const float* __restrict__ attW) {
    int n = blockIdx.x * blockDim.y + threadIdx.y;
    if (n >= NN) return;
    int lane = threadIdx.x;
    float4 aw = ((const float4*)attW)[lane];
    const float4* h4 = (const float4*)g_hseq + n * (TT * HH / 4) + lane;
    float4 hv[16];
    float s[16];
#pragma unroll
    for (int t = 0; t < TT; t++) {
        hv[t] = h4[t * 32];
        float d = hv[t].x * aw.x + hv[t].y * aw.y + hv[t].z * aw.z + hv[t].w * aw.w;
#pragma unroll
        for (int o = 16; o > 0; o >>= 1) d += __shfl_xor_sync(0xffffffffu, d, o);
        s[t] = d;
    }
    float m = s[0];
#pragma unroll
    for (int t = 1; t < TT; t++) m = fmaxf(m, s[t]);
    float sum = 0.f;
#pragma unroll
    for (int t = 0; t < TT; t++) { s[t] = expf(s[t] - m); sum += s[t]; }
    float inv = 1.f / sum;
    float4 c = make_float4(0.f, 0.f, 0.f, 0.f);
#pragma unroll
    for (int t = 0; t < TT; t++) {
        float w = s[t] * inv;
        c.x += w * hv[t].x; c.y += w * hv[t].y; c.z += w * hv[t].z; c.w += w * hv[t].w;
    }
    ((float4*)g_ctx)[n * 32 + lane] = c;
}

// ---------------- launch ----------------

#define SMEM_LAYER ((2 * 64 * SA + 2 * 16 * 264) * 4)

extern "C" void kernel_launch(void* const* d_in, const int* in_sizes, int n_in,
                              void* d_out, int out_size) {
    const float* x   = (const float*)d_in[0];
    const int*   ei  = (const int*)d_in[1];
    const float* ew  = (const float*)d_in[2];
    WPtrs P;
    P.Wc[0] = (const float*)d_in[3];  P.bc[0] = (const float*)d_in[4];
    P.Wl[0] = (const float*)d_in[5];  P.bl[0] = (const float*)d_in[6];
    P.Wc[1] = (const float*)d_in[7];  P.bc[1] = (const float*)d_in[8];
    P.Wl[1] = (const float*)d_in[9];  P.bl[1] = (const float*)d_in[10];
    P.Wc[2] = (const float*)d_in[11]; P.bc[2] = (const float*)d_in[12];
    P.Wl[2] = (const float*)d_in[13]; P.bl[2] = (const float*)d_in[14];
    const float* attW = (const float*)d_in[15];
    const float* outW = (const float*)d_in[17];
    const float* outb = (const float*)d_in[18];
    float* out = (float*)d_out;

    float *p_xT, *p_h0, *p_h1, *p_ctx, *p_bzr, *p_bh;
    uint32_t *p_WzrH, *p_WzrL, *p_WhH, *p_WhL;
    cudaGetSymbolAddress((void**)&p_xT,   g_xT);
    cudaGetSymbolAddress((void**)&p_h0,   g_h0);
    cudaGetSymbolAddress((void**)&p_h1,   g_h1);
    cudaGetSymbolAddress((void**)&p_ctx,  g_ctx);
    cudaGetSymbolAddress((void**)&p_WzrH, g_WzrH);
    cudaGetSymbolAddress((void**)&p_WzrL, g_WzrL);
    cudaGetSymbolAddress((void**)&p_WhH,  g_WhH);
    cudaGetSymbolAddress((void**)&p_WhL,  g_WhL);
    cudaGetSymbolAddress((void**)&p_bzr,  g_bzr);
    cudaGetSymbolAddress((void**)&p_bh,   g_bh);

    cudaFuncSetAttribute(k_layer<0>, cudaFuncAttributeMaxDynamicSharedMemorySize, SMEM_LAYER);
    cudaFuncSetAttribute(k_layer<1>, cudaFuncAttributeMaxDynamicSharedMemorySize, SMEM_LAYER);

    const int GL = (NN + 63) / 64;                  // 157
    const int GX = (NN + 127) / 128;                // 79

    k_prep<<<dim3(HH, 6), HH>>>(P);
    k_init<<<(NN * FF + 255) / 256, 256>>>(x, ei, ew);
    k_scan<<<1, 1024>>>();
    k_scatter<<<(EE + 255) / 256, 256>>>(ei, ew);

    for (int t = 0; t < TT; t++) {
        k_layer<0><<<GL, 256, SMEM_LAYER>>>(p_xT + (size_t)t * NN * FF, p_h0,
                                            p_WzrH, p_WzrL, p_bzr,
                                            p_WhH, p_WhL, p_bh, t);
        k_layer<1><<<GL, 256, SMEM_LAYER>>>(p_h0, p_h1,
                                            p_WzrH + 256 * 256, p_WzrL + 256 * 256, p_bzr + 256,
                                            p_WhH + 256 * 128, p_WhL + 256 * 128, p_bh + 128, t);
    }

    k_attn<<<(NN + 3) / 4, dim3(32, 4)>>>(attW);
    k_proj<<<dim3(GX, 2), 256>>>(p_ctx, outW, outb, out, NN);
}

// round 9
// speedup vs baseline: 1.1159x; 1.1159x over previous
#include <cuda_runtime.h>
#include <math.h>
#include <stdint.h>

#define NN 10000
#define EE 320000
#define FF 128
#define HH 128
#define TT 16
#define OO 128
#define SA 132      // smem A row stride (floats)

// ---------------- static device scratch ----------------
__device__ float g_xT[TT * NN * FF];        // (T,N,F)
__device__ float g_hseq[NN * TT * HH];      // (N,T,H)
__device__ float g_h0[NN * HH];
__device__ float g_h1[NN * HH];
__device__ float g_agg[NN * HH];            // layer-1 per-step aggregation
__device__ float g_agg0[TT * NN * HH];      // layer-0 aggregation, all t (hoisted)
__device__ float g_pre_zr[TT * NN * 256];   // agg0 @ W1zr (no bias)
__device__ float g_pre_h[TT * NN * 128];    // agg0 @ W1h  (no bias)
__device__ float g_zg[NN * HH];             // layer-1 z round-trip
__device__ float g_ctx[NN * HH];
__device__ int   g_rowptr[NN + 1];
__device__ int   g_cursor[NN];
__device__ int   g_cols[EE];
__device__ float g_vals[EE];
__device__ float g_dinv[NN];
__device__ float g_selfn[NN];
// Fused weights pre-split tf32 hi/lo: [l][k][n]; k<128 = agg rows, k>=128 = hp rows.
__device__ uint32_t g_WzrH[2 * 256 * 256];
__device__ uint32_t g_WzrL[2 * 256 * 256];
__device__ uint32_t g_WhH[2 * 256 * 128];
__device__ uint32_t g_WhL[2 * 256 * 128];
__device__ float g_bzr[2 * 256];
__device__ float g_bh[2 * 128];

struct WPtrs {
    const float* Wc[3];
    const float* bc[3];
    const float* Wl[3];
    const float* bl[3];
};

// ---------------- tf32 helpers ----------------
__device__ __forceinline__ uint32_t f2tf(float x) {
    uint32_t r;
    asm("cvt.rna.tf32.f32 %0, %1;" : "=r"(r) : "f"(x));
    return r;
}

__device__ __forceinline__ void mma_tf32(float* c, const uint32_t* a, const uint32_t* b) {
    asm volatile(
        "mma.sync.aligned.m16n8k8.row.col.f32.tf32.tf32.f32 "
        "{%0,%1,%2,%3}, {%4,%5,%6,%7}, {%8,%9}, {%0,%1,%2,%3};\n"
        : "+f"(c[0]), "+f"(c[1]), "+f"(c[2]), "+f"(c[3])
        : "r"(a[0]), "r"(a[1]), "r"(a[2]), "r"(a[3]), "r"(b[0]), "r"(b[1]));
}

// ---------------- preprocessing ----------------

// Boot: transpose x (N,F,T)->(T,N,F), zero h states, build fused hi/lo weights + biases.
__global__ void k_boot(const float* __restrict__ x, WPtrs P) {
    int b = blockIdx.x;
    if (b < 5000) {
        int idx = b * 256 + threadIdx.x;       // over N*F (= 1,280,000 exactly)
        if (idx >= NN * FF) return;
        const float4* xr = (const float4*)(x + (size_t)idx * TT);
        float v[16];
        float4 q;
        q = xr[0]; v[0]=q.x; v[1]=q.y; v[2]=q.z; v[3]=q.w;
        q = xr[1]; v[4]=q.x; v[5]=q.y; v[6]=q.z; v[7]=q.w;
        q = xr[2]; v[8]=q.x; v[9]=q.y; v[10]=q.z; v[11]=q.w;
        q = xr[3]; v[12]=q.x; v[13]=q.y; v[14]=q.z; v[15]=q.w;
#pragma unroll
        for (int t = 0; t < TT; t++)
            g_xT[t * (NN * FF) + idx] = v[t];
        g_h0[idx] = 0.f;
        g_h1[idx] = 0.f;
        return;
    }
    // weight prep: blocks [5000, 5768)
    if (threadIdx.x >= 128) return;
    int b2 = b - 5000;                 // 0..767
    int lg = b2 >> 7;                  // 0..5
    int l = lg / 3, g = lg % 3;
    int i = b2 & 127;
    int j = threadIdx.x;
    const float* Wc = P.Wc[g] + l * HH * HH;
    const float* Wl = P.Wl[g] + l * 2 * HH * HH;
    float c = 0.f;
    for (int k = 0; k < HH; k++) c += Wc[i * HH + k] * Wl[k * HH + j];
    float bot = Wl[(HH + i) * HH + j];
    uint32_t cH = f2tf(c),   cL = f2tf(c - __uint_as_float(cH));
    uint32_t bH = f2tf(bot), bL = f2tf(bot - __uint_as_float(bH));
    if (g < 2) {
        size_t topi = (size_t)l * 256 * 256 + i * 256 + g * HH + j;
        size_t boti = (size_t)l * 256 * 256 + (HH + i) * 256 + g * HH + j;
        g_WzrH[topi] = cH; g_WzrL[topi] = cL;
        g_WzrH[boti] = bH; g_WzrL[boti] = bL;
    } else {
        size_t topi = (size_t)l * 256 * 128 + i * 128 + j;
        size_t boti = (size_t)l * 256 * 128 + (HH + i) * 128 + j;
        g_WhH[topi] = cH; g_WhL[topi] = cL;
        g_WhH[boti] = bH; g_WhL[boti] = bL;
    }
    if (i == 0) {
        const float* bc = P.bc[g] + l * HH;
        const float* bl = P.bl[g] + l * HH;
        float bsum = 0.f;
        for (int k = 0; k < HH; k++) bsum += bc[k] * Wl[k * HH + j];
        bsum += bl[j];
        if (g < 2) g_bzr[l * 256 + g * HH + j] = bsum;
        else       g_bh[l * 128 + j] = bsum;
    }
}

// Count (smem atomics) + degree + scan, single block.
__global__ void k_scan2(const int* __restrict__ ei, const float* __restrict__ ew) {
    extern __shared__ int sm[];
    int* scount = sm;                          // NN ints
    float* sdeg = (float*)(sm + NN);           // NN floats
    int* sdata = sm + 2 * NN;                  // 1024 ints
    __shared__ int s_off;
    int tid = threadIdx.x;
    for (int i = tid; i < NN; i += 1024) { scount[i] = 0; sdeg[i] = 0.f; }
    __syncthreads();
    for (int e = tid; e < EE; e += 1024) {
        int d = ei[EE + e];
        atomicAdd(&scount[d], 1);
        atomicAdd(&sdeg[d], ew[e]);
    }
    __syncthreads();
    for (int i = tid; i < NN; i += 1024) {
        float dinv = rsqrtf(sdeg[i] + 1.0f);
        g_dinv[i] = dinv;
        g_selfn[i] = dinv * dinv;
    }
    if (tid == 0) s_off = 0;
    __syncthreads();
    for (int base = 0; base < NN; base += 1024) {
        int v = (base + tid < NN) ? scount[base + tid] : 0;
        sdata[tid] = v;
        __syncthreads();
        for (int d = 1; d < 1024; d <<= 1) {
            int t2 = (tid >= d) ? sdata[tid - d] : 0;
            __syncthreads();
            sdata[tid] += t2;
            __syncthreads();
        }
        int excl = sdata[tid] - v;
        if (base + tid < NN) {
            g_rowptr[base + tid] = s_off + excl;
            g_cursor[base + tid] = s_off + excl;
        }
        __syncthreads();
        int chunk_total = sdata[1023];
        if (tid == 0) s_off += chunk_total;
        __syncthreads();
    }
    if (tid == 0) g_rowptr[NN] = s_off;
}

__global__ void k_scatter(const int* __restrict__ ei, const float* __restrict__ ew) {
    int e = blockIdx.x * blockDim.x + threadIdx.x;
    if (e >= EE) return;
    int s = ei[e], d = ei[EE + e];
    int p = atomicAdd(&g_cursor[d], 1);
    g_cols[p] = s;
    g_vals[p] = ew[e] * g_dinv[s] * g_dinv[d];
}

// ---------------- SpMM (batched over blockIdx.y) ----------------
__global__ void k_spmm(const float* __restrict__ in, float* __restrict__ out) {
    int row = blockIdx.x * blockDim.y + threadIdx.y;
    if (row >= NN) return;
    int lane = threadIdx.x;
    const float4* in4 = (const float4*)(in + (size_t)blockIdx.y * NN * HH);
    float4* out4 = (float4*)(out + (size_t)blockIdx.y * NN * HH);
    float sn = g_selfn[row];
    float4 hv = in4[row * 32 + lane];
    float ax = sn * hv.x, ay = sn * hv.y, az = sn * hv.z, aw = sn * hv.w;
    float bx = 0.f, by = 0.f, bz = 0.f, bw = 0.f;
    int p = g_rowptr[row], pe = g_rowptr[row + 1];
    for (; p + 3 < pe; p += 4) {
        float v0 = g_vals[p],   v1 = g_vals[p+1], v2 = g_vals[p+2], v3 = g_vals[p+3];
        int   c0 = g_cols[p],   c1 = g_cols[p+1], c2 = g_cols[p+2], c3 = g_cols[p+3];
        float4 b0 = in4[c0 * 32 + lane];
        float4 b1 = in4[c1 * 32 + lane];
        float4 b2 = in4[c2 * 32 + lane];
        float4 b3 = in4[c3 * 32 + lane];
        ax += v0 * b0.x; ay += v0 * b0.y; az += v0 * b0.z; aw += v0 * b0.w;
        bx += v1 * b1.x; by += v1 * b1.y; bz += v1 * b1.z; bw += v1 * b1.w;
        ax += v2 * b2.x; ay += v2 * b2.y; az += v2 * b2.z; aw += v2 * b2.w;
        bx += v3 * b3.x; by += v3 * b3.y; bz += v3 * b3.z; bw += v3 * b3.w;
    }
    for (; p < pe; p++) {
        float v0 = g_vals[p]; int c0 = g_cols[p];
        float4 b0 = in4[c0 * 32 + lane];
        ax += v0 * b0.x; ay += v0 * b0.y; az += v0 * b0.z; aw += v0 * b0.w;
    }
    out4[row * 32 + lane] = make_float4(ax + bx, ay + by, az + bz, aw + bw);
}

// ---------------- shared 3xTF32 GEMM phase ----------------
// 64 x (NT*32) tile, K in 8-row slabs; A fp32 in smem (sA cols 0-127, sA2 cols 128-255
// selected by absolute k = kt + KOFF), B pre-split tf32 hi/lo in global.
// 8 warps, layout 2m x 4n. Caller owns acc init and epilogue.
template<int NT, int KLEN, int KOFF>
__device__ __forceinline__ void gemm_phase(
    const float* sA, const float* sA2, uint32_t* sBh, uint32_t* sBl,
    const uint32_t* __restrict__ Bh, const uint32_t* __restrict__ Bl,
    int tid, int lane, int warp_m, int warp_n, float (&acc)[2][NT][4]) {
    constexpr int NB = NT * 32;
    constexpr int SB = NB + 8;
    for (int kt = 0; kt < KLEN; kt += 8) {
#pragma unroll
        for (int i = tid * 4; i < 8 * NB; i += 1024) {
            int k = i / NB, n = i % NB;
            *(uint4*)&sBh[k * SB + n] = *(const uint4*)&Bh[(size_t)(kt + k) * NB + n];
            *(uint4*)&sBl[k * SB + n] = *(const uint4*)&Bl[(size_t)(kt + k) * NB + n];
        }
        __syncthreads();
        const int kAbs = kt + KOFF;
        const float* Asrc = (kAbs < 128) ? sA : sA2;
        const int colb = (kAbs & 127) + (lane & 3);
        uint32_t ah[2][4], al[2][4];
#pragma unroll
        for (int mt = 0; mt < 2; mt++) {
            int ar = (warp_m * 32 + mt * 16 + (lane >> 2)) * SA + colb;
            float a0 = Asrc[ar],     a1 = Asrc[ar + 8 * SA];
            float a2 = Asrc[ar + 4], a3 = Asrc[ar + 8 * SA + 4];
            ah[mt][0] = f2tf(a0); al[mt][0] = f2tf(a0 - __uint_as_float(ah[mt][0]));
            ah[mt][1] = f2tf(a1); al[mt][1] = f2tf(a1 - __uint_as_float(ah[mt][1]));
            ah[mt][2] = f2tf(a2); al[mt][2] = f2tf(a2 - __uint_as_float(ah[mt][2]));
            ah[mt][3] = f2tf(a3); al[mt][3] = f2tf(a3 - __uint_as_float(ah[mt][3]));
        }
#pragma unroll
        for (int nt = 0; nt < NT; nt++) {
            int ncol = warp_n * (NT * 8) + nt * 8 + (lane >> 2);
            int kr = (lane & 3) * SB;
            uint32_t bh[2], bl[2];
            bh[0] = sBh[kr + ncol]; bh[1] = sBh[kr + 4 * SB + ncol];
            bl[0] = sBl[kr + ncol]; bl[1] = sBl[kr + 4 * SB + ncol];
#pragma unroll
            for (int mt = 0; mt < 2; mt++) {
                mma_tf32(acc[mt][nt], ah[mt], bh);
                mma_tf32(acc[mt][nt], ah[mt], bl);
                mma_tf32(acc[mt][nt], al[mt], bh);
            }
        }
        __syncthreads();
    }
}

// ---------------- pre-pass batched GEMM: out = A(160000x128) @ W(128xNB) ----------------
template<int NT>
__global__ void __launch_bounds__(256, 2)
k_pre(const float* __restrict__ A, const uint32_t* __restrict__ BH,
      const uint32_t* __restrict__ BL, float* __restrict__ outp) {
    extern __shared__ float smem[];
    float* sA = smem;
    uint32_t* sBh = (uint32_t*)(smem + 64 * SA);
    uint32_t* sBl = sBh + 8 * 264;
    const int tid = threadIdx.x, lane = tid & 31, wid = tid >> 5;
    const int warp_m = wid & 1, warp_n = wid >> 1;
    const int row0 = blockIdx.x * 64;      // grid 2500, exact
    for (int i = tid; i < 64 * 32; i += 256) {
        int r = i >> 5, c4 = i & 31;
        *(float4*)&sA[r * SA + c4 * 4] = ((const float4*)A)[(size_t)(row0 + r) * 32 + c4];
    }
    __syncthreads();
    float acc[2][NT][4];
#pragma unroll
    for (int i = 0; i < 2; i++)
#pragma unroll
        for (int j = 0; j < NT; j++)
#pragma unroll
            for (int q = 0; q < 4; q++) acc[i][j][q] = 0.f;
    gemm_phase<NT, 128, 0>(sA, sA, sBh, sBl, BH, BL, tid, lane, warp_m, warp_n, acc);
#pragma unroll
    for (int mt = 0; mt < 2; mt++)
#pragma unroll
        for (int nt = 0; nt < NT; nt++) {
            int gcol = warp_n * (NT * 8) + nt * 8 + (lane & 3) * 2;
#pragma unroll
            for (int half = 0; half < 2; half++) {
                int grow = row0 + warp_m * 32 + mt * 16 + (lane >> 2) + half * 8;
                *(float2*)&outp[(size_t)grow * (NT * 32) + gcol] =
                    make_float2(acc[mt][nt][half * 2 + 0], acc[mt][nt][half * 2 + 1]);
            }
        }
}

// ---------------- fused cell: gate + candidate + blend ----------------
// PRE=1 (layer0): acc init from pre arrays, K=128 (hp half only), z kept in smem (sA).
// PRE=0 (layer1): sA = agg (global), K=256, z via g_zg.
template<int PRE, int WSEQ>
__global__ void __launch_bounds__(256, 2)
k_cell(const float* __restrict__ agg, const float* __restrict__ preZr,
       const float* __restrict__ preH, float* __restrict__ hstate,
       const uint32_t* __restrict__ WzrH, const uint32_t* __restrict__ WzrL,
       const float* __restrict__ bzr,
       const uint32_t* __restrict__ WhH, const uint32_t* __restrict__ WhL,
       const float* __restrict__ bh, int t) {
    extern __shared__ float smem[];
    float* sA  = smem;                       // agg (PRE=0) | z-store (PRE=1)
    float* sA2 = smem + 64 * SA;             // hp -> r*hp
    uint32_t* sBh = (uint32_t*)(smem + 2 * 64 * SA);
    uint32_t* sBl = sBh + 8 * 264;
    const int tid = threadIdx.x, lane = tid & 31, wid = tid >> 5;
    const int warp_m = wid & 1, warp_n = wid >> 1;
    const int row0 = blockIdx.x * 64;

    // phase 0: load hp (and agg for PRE=0)
    for (int i = tid; i < 64 * 32; i += 256) {
        int r = i >> 5, c4 = i & 31;
        int grow = row0 + r;
        float4 v = (grow < NN) ? ((const float4*)hstate)[grow * 32 + c4]
                               : make_float4(0.f, 0.f, 0.f, 0.f);
        *(float4*)&sA2[r * SA + c4 * 4] = v;
        if (!PRE) {
            float4 a = (grow < NN) ? ((const float4*)agg)[grow * 32 + c4]
                                   : make_float4(0.f, 0.f, 0.f, 0.f);
            *(float4*)&sA[r * SA + c4 * 4] = a;
        }
    }
    __syncthreads();

    // ---- gate (N=256) ----
    {
        float acc[2][8][4];
#pragma unroll
        for (int mt = 0; mt < 2; mt++)
#pragma unroll
            for (int nt = 0; nt < 8; nt++) {
                int gcol = warp_n * 64 + nt * 8 + (lane & 3) * 2;
#pragma unroll
                for (int half = 0; half < 2; half++) {
                    float2 v = make_float2(0.f, 0.f);
                    if (PRE) {
                        int grow = row0 + warp_m * 32 + mt * 16 + (lane >> 2) + half * 8;
                        if (grow < NN)
                            v = *(const float2*)&preZr[(size_t)grow * 256 + gcol];
                    }
                    acc[mt][nt][half * 2 + 0] = v.x;
                    acc[mt][nt][half * 2 + 1] = v.y;
                }
            }
        if (PRE)
            gemm_phase<8, 128, 128>(sA, sA2, sBh, sBl, WzrH, WzrL,
                                    tid, lane, warp_m, warp_n, acc);
        else
            gemm_phase<8, 256, 0>(sA, sA2, sBh, sBl, WzrH, WzrL,
                                  tid, lane, warp_m, warp_n, acc);
#pragma unroll
        for (int mt = 0; mt < 2; mt++)
#pragma unroll
            for (int nt = 0; nt < 8; nt++) {
                int gcol = warp_n * 64 + nt * 8 + (lane & 3) * 2;
                float b0 = bzr[gcol], b1 = bzr[gcol + 1];
#pragma unroll
                for (int half = 0; half < 2; half++) {
                    int lr = warp_m * 32 + mt * 16 + (lane >> 2) + half * 8;
                    int grow = row0 + lr;
                    float v0 = 1.f / (1.f + expf(-(acc[mt][nt][half * 2 + 0] + b0)));
                    float v1 = 1.f / (1.f + expf(-(acc[mt][nt][half * 2 + 1] + b1)));
                    if (gcol < 128) {
                        if (PRE)
                            *(float2*)&sA[lr * SA + gcol] = make_float2(v0, v1);
                        else if (grow < NN)
                            *(float2*)&g_zg[(size_t)grow * 128 + gcol] = make_float2(v0, v1);
                    } else {
                        int lc = gcol - 128;
                        float hp0 = sA2[lr * SA + lc];
                        float hp1 = sA2[lr * SA + lc + 1];
                        sA2[lr * SA + lc]     = v0 * hp0;
                        sA2[lr * SA + lc + 1] = v1 * hp1;
                    }
                }
            }
    }
    // (first __syncthreads inside next gemm_phase orders sA/sA2 writes before reads)

    // ---- candidate (N=128) + blend ----
    {
        float acc[2][4][4];
#pragma unroll
        for (int mt = 0; mt < 2; mt++)
#pragma unroll
            for (int nt = 0; nt < 4; nt++) {
                int gcol = warp_n * 32 + nt * 8 + (lane & 3) * 2;
#pragma unroll
                for (int half = 0; half < 2; half++) {
                    float2 v = make_float2(0.f, 0.f);
                    if (PRE) {
                        int grow = row0 + warp_m * 32 + mt * 16 + (lane >> 2) + half * 8;
                        if (grow < NN)
                            v = *(const float2*)&preH[(size_t)grow * 128 + gcol];
                    }
                    acc[mt][nt][half * 2 + 0] = v.x;
                    acc[mt][nt][half * 2 + 1] = v.y;
                }
            }
        if (PRE)
            gemm_phase<4, 128, 128>(sA, sA2, sBh, sBl, WhH, WhL,
                                    tid, lane, warp_m, warp_n, acc);
        else
            gemm_phase<4, 256, 0>(sA, sA2, sBh, sBl, WhH, WhL,
                                  tid, lane, warp_m, warp_n, acc);
#pragma unroll
        for (int mt = 0; mt < 2; mt++)
#pragma unroll
            for (int nt = 0; nt < 4; nt++) {
                int gcol = warp_n * 32 + nt * 8 + (lane & 3) * 2;
                float b0 = bh[gcol], b1 = bh[gcol + 1];
#pragma unroll
                for (int half = 0; half < 2; half++) {
                    int lr = warp_m * 32 + mt * 16 + (lane >> 2) + half * 8;
                    int grow = row0 + lr;
                    if (grow >= NN) continue;
                    size_t base = (size_t)grow * 128 + gcol;
                    float ht0 = tanhf(acc[mt][nt][half * 2 + 0] + b0);
                    float ht1 = tanhf(acc[mt][nt][half * 2 + 1] + b1);
                    float2 zv = PRE ? *(const float2*)&sA[lr * SA + gcol]
                                    : *(const float2*)&g_zg[base];
                    float2 hv = *(const float2*)&hstate[base];
                    float hn0 = zv.x * hv.x + (1.f - zv.x) * ht0;
                    float hn1 = zv.y * hv.y + (1.f - zv.y) * ht1;
                    *(float2*)&hstate[base] = make_float2(hn0, hn1);
                    if (WSEQ) {
                        size_t sb = (size_t)grow * (TT * HH) + t * HH + gcol;
                        *(float2*)&g_hseq[sb] = make_float2(hn0, hn1);
                    }
                }
            }
    }
}

// ---------------- temporal attention ----------------
__global__ void __launch_bounds__(128)
k_attn(const float* __restrict__ attW) {
    int n = blockIdx.x * blockDim.y + threadIdx.y;
    if (n >= NN) return;
    int lane = threadIdx.x;
    float4 aw = ((const float4*)attW)[lane];
    const float4* h4 = (const float4*)g_hseq + n * (TT * HH / 4) + lane;
    float4 hv[16];
    float s[16];
#pragma unroll
    for (int t = 0; t < TT; t++) {
        hv[t] = h4[t * 32];
        float d = hv[t].x * aw.x + hv[t].y * aw.y + hv[t].z * aw.z + hv[t].w * aw.w;
#pragma unroll
        for (int o = 16; o > 0; o >>= 1) d += __shfl_xor_sync(0xffffffffu, d, o);
        s[t] = d;
    }
    float m = s[0];
#pragma unroll
    for (int t = 1; t < TT; t++) m = fmaxf(m, s[t]);
    float sum = 0.f;
#pragma unroll
    for (int t = 0; t < TT; t++) { s[t] = expf(s[t] - m); sum += s[t]; }
    float inv = 1.f / sum;
    float4 c = make_float4(0.f, 0.f, 0.f, 0.f);
#pragma unroll
    for (int t = 0; t < TT; t++) {
        float w = s[t] * inv;
        c.x += w * hv[t].x; c.y += w * hv[t].y; c.z += w * hv[t].z; c.w += w * hv[t].w;
    }
    ((float4*)g_ctx)[n * 32 + lane] = c;
}

// ---------------- final projection (3xTF32, inline conversion) ----------------
__global__ void __launch_bounds__(256)
k_proj(const float* __restrict__ A1, const float* __restrict__ B,
       const float* __restrict__ bias, float* __restrict__ Cout, int M) {
    constexpr int SAp = 20;
    constexpr int SB = 72;
    __shared__ float sAh[128 * SAp];
    __shared__ float sAl[128 * SAp];
    __shared__ float sBh[16 * SB];
    __shared__ float sBl[16 * SB];
    const int tid = threadIdx.x, lane = tid & 31, wid = tid >> 5;
    const int warp_m = wid & 3, warp_n = wid >> 2;
    const int row0 = blockIdx.x * 128;
    const int col0 = blockIdx.y * 64;
    float acc[2][4][4];
#pragma unroll
    for (int i = 0; i < 2; i++)
#pragma unroll
        for (int j = 0; j < 4; j++)
#pragma unroll
            for (int q = 0; q < 4; q++) acc[i][j][q] = 0.f;

    for (int kt = 0; kt < 128; kt += 16) {
#pragma unroll
        for (int i = 0; i < 2; i++) {
            int lid = tid + i * 256;
            int m = lid >> 2, kq = (lid & 3) * 4;
            int grow = row0 + m;
            float4 a = (grow < M) ? *(const float4*)(A1 + (size_t)grow * 128 + kt + kq)
                                  : make_float4(0.f, 0.f, 0.f, 0.f);
            float4 h4, l4;
            h4.x = __uint_as_float(f2tf(a.x)); l4.x = __uint_as_float(f2tf(a.x - h4.x));
            h4.y = __uint_as_float(f2tf(a.y)); l4.y = __uint_as_float(f2tf(a.y - h4.y));
            h4.z = __uint_as_float(f2tf(a.z)); l4.z = __uint_as_float(f2tf(a.z - h4.z));
            h4.w = __uint_as_float(f2tf(a.w)); l4.w = __uint_as_float(f2tf(a.w - h4.w));
            *(float4*)&sAh[m * SAp + kq] = h4;
            *(float4*)&sAl[m * SAp + kq] = l4;
        }
        {
            int k = tid >> 4, nq = (tid & 15) * 4;
            float4 b = *(const float4*)&B[(size_t)(kt + k) * 128 + col0 + nq];
            float4 h4, l4;
            h4.x = __uint_as_float(f2tf(b.x)); l4.x = __uint_as_float(f2tf(b.x - h4.x));
            h4.y = __uint_as_float(f2tf(b.y)); l4.y = __uint_as_float(f2tf(b.y - h4.y));
            h4.z = __uint_as_float(f2tf(b.z)); l4.z = __uint_as_float(f2tf(b.z - h4.z));
            h4.w = __uint_as_float(f2tf(b.w)); l4.w = __uint_as_float(f2tf(b.w - h4.w));
            *(float4*)&sBh[k * SB + nq] = h4;
            *(float4*)&sBl[k * SB + nq] = l4;
        }
        __syncthreads();
#pragma unroll
        for (int k0 = 0; k0 < 16; k0 += 8) {
            uint32_t ah[2][4], al[2][4];
#pragma unroll
            for (int mt = 0; mt < 2; mt++) {
                int r0 = (warp_m * 32 + mt * 16 + (lane >> 2)) * SAp;
                int c0k = k0 + (lane & 3);
                ah[mt][0] = __float_as_uint(sAh[r0 + c0k]);
                ah[mt][1] = __float_as_uint(sAh[r0 + 8 * SAp + c0k]);
                ah[mt][2] = __float_as_uint(sAh[r0 + c0k + 4]);
                ah[mt][3] = __float_as_uint(sAh[r0 + 8 * SAp + c0k + 4]);
                al[mt][0] = __float_as_uint(sAl[r0 + c0k]);
                al[mt][1] = __float_as_uint(sAl[r0 + 8 * SAp + c0k]);
                al[mt][2] = __float_as_uint(sAl[r0 + c0k + 4]);
                al[mt][3] = __float_as_uint(sAl[r0 + 8 * SAp + c0k + 4]);
            }
#pragma unroll
            for (int nt = 0; nt < 4; nt++) {
                int ncol = warp_n * 32 + nt * 8 + (lane >> 2);
                int kr = (k0 + (lane & 3)) * SB;
                uint32_t bh[2], bl[2];
                bh[0] = __float_as_uint(sBh[kr + ncol]);
                bh[1] = __float_as_uint(sBh[kr + 4 * SB + ncol]);
                bl[0] = __float_as_uint(sBl[kr + ncol]);
                bl[1] = __float_as_uint(sBl[kr + 4 * SB + ncol]);
#pragma unroll
                for (int mt = 0; mt < 2; mt++) {
                    mma_tf32(acc[mt][nt], ah[mt], bh);
                    mma_tf32(acc[mt][nt], ah[mt], bl);
                    mma_tf32(acc[mt][nt], al[mt], bh);
                }
            }
        }
        __syncthreads();
    }
#pragma unroll
    for (int mt = 0; mt < 2; mt++)
#pragma unroll
        for (int nt = 0; nt < 4; nt++) {
            int gcol = col0 + warp_n * 32 + nt * 8 + (lane & 3) * 2;
            float b0 = bias[gcol], b1 = bias[gcol + 1];
#pragma unroll
            for (int half = 0; half < 2; half++) {
                int row = row0 + warp_m * 32 + mt * 16 + (lane >> 2) + half * 8;
                if (row >= M) continue;
                *(float2*)&Cout[(size_t)row * 128 + gcol] =
                    make_float2(acc[mt][nt][half * 2 + 0] + b0,
                                acc[mt][nt][half * 2 + 1] + b1);
            }
        }
}

// ---------------- launch ----------------

#define SMEM_CELL ((2 * 64 * SA) * 4 + 2 * 8 * 264 * 4)     // 84480
#define SMEM_PRE  ((64 * SA) * 4 + 2 * 8 * 264 * 4)         // 50688
#define SMEM_SCAN ((2 * NN + 1024) * 4)                     // 84096

extern "C" void kernel_launch(void* const* d_in, const int* in_sizes, int n_in,
                              void* d_out, int out_size) {
    const float* x   = (const float*)d_in[0];
    const int*   ei  = (const int*)d_in[1];
    const float* ew  = (const float*)d_in[2];
    WPtrs P;
    P.Wc[0] = (const float*)d_in[3];  P.bc[0] = (const float*)d_in[4];
    P.Wl[0] = (const float*)d_in[5];  P.bl[0] = (const float*)d_in[6];
    P.Wc[1] = (const float*)d_in[7];  P.bc[1] = (const float*)d_in[8];
    P.Wl[1] = (const float*)d_in[9];  P.bl[1] = (const float*)d_in[10];
    P.Wc[2] = (const float*)d_in[11]; P.bc[2] = (const float*)d_in[12];
    P.Wl[2] = (const float*)d_in[13]; P.bl[2] = (const float*)d_in[14];
    const float* attW = (const float*)d_in[15];
    const float* outW = (const float*)d_in[17];
    const float* outb = (const float*)d_in[18];
    float* out = (float*)d_out;

    float *p_xT, *p_h0, *p_h1, *p_agg, *p_agg0, *p_preZr, *p_preH, *p_ctx, *p_bzr, *p_bh;
    uint32_t *p_WzrH, *p_WzrL, *p_WhH, *p_WhL;
    cudaGetSymbolAddress((void**)&p_xT,    g_xT);
    cudaGetSymbolAddress((void**)&p_h0,    g_h0);
    cudaGetSymbolAddress((void**)&p_h1,    g_h1);
    cudaGetSymbolAddress((void**)&p_agg,   g_agg);
    cudaGetSymbolAddress((void**)&p_agg0,  g_agg0);
    cudaGetSymbolAddress((void**)&p_preZr, g_pre_zr);
    cudaGetSymbolAddress((void**)&p_preH,  g_pre_h);
    cudaGetSymbolAddress((void**)&p_ctx,   g_ctx);
    cudaGetSymbolAddress((void**)&p_WzrH,  g_WzrH);
    cudaGetSymbolAddress((void**)&p_WzrL,  g_WzrL);
    cudaGetSymbolAddress((void**)&p_WhH,   g_WhH);
    cudaGetSymbolAddress((void**)&p_WhL,   g_WhL);
    cudaGetSymbolAddress((void**)&p_bzr,   g_bzr);
    cudaGetSymbolAddress((void**)&p_bh,    g_bh);

    cudaFuncSetAttribute(k_cell<1,0>, cudaFuncAttributeMaxDynamicSharedMemorySize, SMEM_CELL);
    cudaFuncSetAttribute(k_cell<0,1>, cudaFuncAttributeMaxDynamicSharedMemorySize, SMEM_CELL);
    cudaFuncSetAttribute(k_pre<8>,   cudaFuncAttributeMaxDynamicSharedMemorySize, SMEM_PRE);
    cudaFuncSetAttribute(k_pre<4>,   cudaFuncAttributeMaxDynamicSharedMemorySize, SMEM_PRE);
    cudaFuncSetAttribute(k_scan2,    cudaFuncAttributeMaxDynamicSharedMemorySize, SMEM_SCAN);

    const int GC = (NN + 63) / 64;                  // 157
    const int GX = (NN + 127) / 128;                // 79

    k_boot<<<5768, 256>>>(x, P);
    k_scan2<<<1, 1024, SMEM_SCAN>>>(ei, ew);
    k_scatter<<<(EE + 255) / 256, 256>>>(ei, ew);
    k_spmm<<<dim3(1250, 16), dim3(32, 8)>>>(p_xT, p_agg0);                 // all-t layer-0 agg
    k_pre<8><<<2500, 256, SMEM_PRE>>>(p_agg0, p_WzrH, p_WzrL, p_preZr);    // agg0 @ W1zr
    k_pre<4><<<2500, 256, SMEM_PRE>>>(p_agg0, p_WhH, p_WhL, p_preH);       // agg0 @ W1h

    for (int t = 0; t < TT; t++) {
        k_cell<1,0><<<GC, 256, SMEM_CELL>>>(nullptr,
            p_preZr + (size_t)t * NN * 256, p_preH + (size_t)t * NN * 128, p_h0,
            p_WzrH + 128 * 256, p_WzrL + 128 * 256, p_bzr,
            p_WhH + 128 * 128, p_WhL + 128 * 128, p_bh, t);
        k_spmm<<<dim3(1250, 1), dim3(32, 8)>>>(p_h0, p_agg);
        k_cell<0,1><<<GC, 256, SMEM_CELL>>>(p_agg, nullptr, nullptr, p_h1,
            p_WzrH + 256 * 256, p_WzrL + 256 * 256, p_bzr + 256,
            p_WhH + 256 * 128, p_WhL + 256 * 128, p_bh + 128, t);
    }

    k_attn<<<(NN + 3) / 4, dim3(32, 4)>>>(attW);
    k_proj<<<dim3(GX, 2), 256>>>(p_ctx, outW, outb, out, NN);
}

// round 12
// speedup vs baseline: 1.4216x; 1.2739x over previous
#include <cuda_runtime.h>
#include <math.h>
#include <stdint.h>

#define NN 10000
#define EE 320000
#define FF 128
#define HH 128
#define TT 16
#define OO 128
#define SA 132      // smem A row stride (floats)

// ---------------- static device scratch ----------------
__device__ float g_xT[TT * NN * FF];        // (T,N,F)
__device__ float g_hseq[NN * TT * HH];      // (N,T,H)
__device__ float g_h0[2 * NN * HH];         // layer-0 state, double-buffered
__device__ float g_h1[NN * HH];
__device__ float g_agg[NN * HH];            // layer-1 per-step aggregation
__device__ float g_agg0[TT * NN * HH];      // layer-0 aggregation, all t (hoisted)
__device__ float g_pre_zr[TT * NN * 256];   // agg0 @ W1zr (no bias)
__device__ float g_pre_h[TT * NN * 128];    // agg0 @ W1h  (no bias)
__device__ float g_zg[NN * HH];             // layer-1 z round-trip
__device__ float g_ctx[NN * HH];
__device__ int   g_rowptr[NN + 1];
__device__ int   g_cursor[NN];
__device__ int   g_cols[EE];
__device__ float g_vals[EE];
__device__ float g_dinv[NN];
__device__ float g_selfn[NN];
// Fused weights pre-split tf32 hi/lo: [l][k][n]; k<128 = agg rows, k>=128 = hp rows.
__device__ uint32_t g_WzrH[2 * 256 * 256];
__device__ uint32_t g_WzrL[2 * 256 * 256];
__device__ uint32_t g_WhH[2 * 256 * 128];
__device__ uint32_t g_WhL[2 * 256 * 128];
__device__ float g_bzr[2 * 256];
__device__ float g_bh[2 * 128];

struct WPtrs {
    const float* Wc[3];
    const float* bc[3];
    const float* Wl[3];
    const float* bl[3];
};

// ---------------- tf32 helpers ----------------
__device__ __forceinline__ uint32_t f2tf(float x) {
    uint32_t r;
    asm("cvt.rna.tf32.f32 %0, %1;" : "=r"(r) : "f"(x));
    return r;
}

__device__ __forceinline__ void mma_tf32(float* c, const uint32_t* a, const uint32_t* b) {
    asm volatile(
        "mma.sync.aligned.m16n8k8.row.col.f32.tf32.tf32.f32 "
        "{%0,%1,%2,%3}, {%4,%5,%6,%7}, {%8,%9}, {%0,%1,%2,%3};\n"
        : "+f"(c[0]), "+f"(c[1]), "+f"(c[2]), "+f"(c[3])
        : "r"(a[0]), "r"(a[1]), "r"(a[2]), "r"(a[3]), "r"(b[0]), "r"(b[1]));
}

// ---------------- preprocessing ----------------

// Boot: transpose x (N,F,T)->(T,N,F), zero h states, build fused hi/lo weights + biases.
__global__ void k_boot(const float* __restrict__ x, WPtrs P) {
    int b = blockIdx.x;
    if (b < 5000) {
        int idx = b * 256 + threadIdx.x;       // over N*F (= 1,280,000 exactly)
        if (idx >= NN * FF) return;
        const float4* xr = (const float4*)(x + (size_t)idx * TT);
        float v[16];
        float4 q;
        q = xr[0]; v[0]=q.x; v[1]=q.y; v[2]=q.z; v[3]=q.w;
        q = xr[1]; v[4]=q.x; v[5]=q.y; v[6]=q.z; v[7]=q.w;
        q = xr[2]; v[8]=q.x; v[9]=q.y; v[10]=q.z; v[11]=q.w;
        q = xr[3]; v[12]=q.x; v[13]=q.y; v[14]=q.z; v[15]=q.w;
#pragma unroll
        for (int t = 0; t < TT; t++)
            g_xT[t * (NN * FF) + idx] = v[t];
        g_h0[idx] = 0.f;                       // buffer 0 = initial state
        g_h1[idx] = 0.f;
        return;
    }
    // weight prep: blocks [5000, 5768)
    if (threadIdx.x >= 128) return;
    int b2 = b - 5000;                 // 0..767
    int lg = b2 >> 7;                  // 0..5
    int l = lg / 3, g = lg % 3;
    int i = b2 & 127;
    int j = threadIdx.x;
    const float* Wc = P.Wc[g] + l * HH * HH;
    const float* Wl = P.Wl[g] + l * 2 * HH * HH;
    float c = 0.f;
    for (int k = 0; k < HH; k++) c += Wc[i * HH + k] * Wl[k * HH + j];
    float bot = Wl[(HH + i) * HH + j];
    uint32_t cH = f2tf(c),   cL = f2tf(c - __uint_as_float(cH));
    uint32_t bH = f2tf(bot), bL = f2tf(bot - __uint_as_float(bH));
    if (g < 2) {
        size_t topi = (size_t)l * 256 * 256 + i * 256 + g * HH + j;
        size_t boti = (size_t)l * 256 * 256 + (HH + i) * 256 + g * HH + j;
        g_WzrH[topi] = cH; g_WzrL[topi] = cL;
        g_WzrH[boti] = bH; g_WzrL[boti] = bL;
    } else {
        size_t topi = (size_t)l * 256 * 128 + i * 128 + j;
        size_t boti = (size_t)l * 256 * 128 + (HH + i) * 128 + j;
        g_WhH[topi] = cH; g_WhL[topi] = cL;
        g_WhH[boti] = bH; g_WhL[boti] = bL;
    }
    if (i == 0) {
        const float* bc = P.bc[g] + l * HH;
        const float* bl = P.bl[g] + l * HH;
        float bsum = 0.f;
        for (int k = 0; k < HH; k++) bsum += bc[k] * Wl[k * HH + j];
        bsum += bl[j];
        if (g < 2) g_bzr[l * 256 + g * HH + j] = bsum;
        else       g_bh[l * 128 + j] = bsum;
    }
}

// Count (smem atomics) + degree + scan, single block.
__global__ void k_scan2(const int* __restrict__ ei, const float* __restrict__ ew) {
    extern __shared__ int sm[];
    int* scount = sm;                          // NN ints
    float* sdeg = (float*)(sm + NN);           // NN floats
    int* sdata = sm + 2 * NN;                  // 1024 ints
    __shared__ int s_off;
    int tid = threadIdx.x;
    for (int i = tid; i < NN; i += 1024) { scount[i] = 0; sdeg[i] = 0.f; }
    __syncthreads();
    for (int e = tid; e < EE; e += 1024) {
        int d = ei[EE + e];
        atomicAdd(&scount[d], 1);
        atomicAdd(&sdeg[d], ew[e]);
    }
    __syncthreads();
    for (int i = tid; i < NN; i += 1024) {
        float dinv = rsqrtf(sdeg[i] + 1.0f);
        g_dinv[i] = dinv;
        g_selfn[i] = dinv * dinv;
    }
    if (tid == 0) s_off = 0;
    __syncthreads();
    for (int base = 0; base < NN; base += 1024) {
        int v = (base + tid < NN) ? scount[base + tid] : 0;
        sdata[tid] = v;
        __syncthreads();
        for (int d = 1; d < 1024; d <<= 1) {
            int t2 = (tid >= d) ? sdata[tid - d] : 0;
            __syncthreads();
            sdata[tid] += t2;
            __syncthreads();
        }
        int excl = sdata[tid] - v;
        if (base + tid < NN) {
            g_rowptr[base + tid] = s_off + excl;
            g_cursor[base + tid] = s_off + excl;
        }
        __syncthreads();
        int chunk_total = sdata[1023];
        if (tid == 0) s_off += chunk_total;
        __syncthreads();
    }
    if (tid == 0) g_rowptr[NN] = s_off;
}

__global__ void k_scatter(const int* __restrict__ ei, const float* __restrict__ ew) {
    int e = blockIdx.x * blockDim.x + threadIdx.x;
    if (e >= EE) return;
    int s = ei[e], d = ei[EE + e];
    int p = atomicAdd(&g_cursor[d], 1);
    g_cols[p] = s;
    g_vals[p] = ew[e] * g_dinv[s] * g_dinv[d];
}

// ---------------- SpMM (batched over blockIdx.y) ----------------
__global__ void k_spmm(const float* __restrict__ in, float* __restrict__ out) {
    int row = blockIdx.x * blockDim.y + threadIdx.y;
    if (row >= NN) return;
    int lane = threadIdx.x;
    const float4* in4 = (const float4*)(in + (size_t)blockIdx.y * NN * HH);
    float4* out4 = (float4*)(out + (size_t)blockIdx.y * NN * HH);
    float sn = g_selfn[row];
    float4 hv = in4[row * 32 + lane];
    float ax = sn * hv.x, ay = sn * hv.y, az = sn * hv.z, aw = sn * hv.w;
    float bx = 0.f, by = 0.f, bz = 0.f, bw = 0.f;
    int p = g_rowptr[row], pe = g_rowptr[row + 1];
    for (; p + 3 < pe; p += 4) {
        float v0 = g_vals[p],   v1 = g_vals[p+1], v2 = g_vals[p+2], v3 = g_vals[p+3];
        int   c0 = g_cols[p],   c1 = g_cols[p+1], c2 = g_cols[p+2], c3 = g_cols[p+3];
        float4 b0 = in4[c0 * 32 + lane];
        float4 b1 = in4[c1 * 32 + lane];
        float4 b2 = in4[c2 * 32 + lane];
        float4 b3 = in4[c3 * 32 + lane];
        ax += v0 * b0.x; ay += v0 * b0.y; az += v0 * b0.z; aw += v0 * b0.w;
        bx += v1 * b1.x; by += v1 * b1.y; bz += v1 * b1.z; bw += v1 * b1.w;
        ax += v2 * b2.x; ay += v2 * b2.y; az += v2 * b2.z; aw += v2 * b2.w;
        bx += v3 * b3.x; by += v3 * b3.y; bz += v3 * b3.z; bw += v3 * b3.w;
    }
    for (; p < pe; p++) {
        float v0 = g_vals[p]; int c0 = g_cols[p];
        float4 b0 = in4[c0 * 32 + lane];
        ax += v0 * b0.x; ay += v0 * b0.y; az += v0 * b0.z; aw += v0 * b0.w;
    }
    out4[row * 32 + lane] = make_float4(ax + bx, ay + by, az + bz, aw + bw);
}

// ---------------- shared 3xTF32 GEMM phase ----------------
template<int NT, int KLEN, int KOFF>
__device__ __forceinline__ void gemm_phase(
    const float* sA, const float* sA2, uint32_t* sBh, uint32_t* sBl,
    const uint32_t* __restrict__ Bh, const uint32_t* __restrict__ Bl,
    int tid, int lane, int warp_m, int warp_n, float (&acc)[2][NT][4]) {
    constexpr int NB = NT * 32;
    constexpr int SB = NB + 8;
    for (int kt = 0; kt < KLEN; kt += 8) {
#pragma unroll
        for (int i = tid * 4; i < 8 * NB; i += 1024) {
            int k = i / NB, n = i % NB;
            *(uint4*)&sBh[k * SB + n] = *(const uint4*)&Bh[(size_t)(kt + k) * NB + n];
            *(uint4*)&sBl[k * SB + n] = *(const uint4*)&Bl[(size_t)(kt + k) * NB + n];
        }
        __syncthreads();
        const int kAbs = kt + KOFF;
        const float* Asrc = (kAbs < 128) ? sA : sA2;
        const int colb = (kAbs & 127) + (lane & 3);
        uint32_t ah[2][4], al[2][4];
#pragma unroll
        for (int mt = 0; mt < 2; mt++) {
            int ar = (warp_m * 32 + mt * 16 + (lane >> 2)) * SA + colb;
            float a0 = Asrc[ar],     a1 = Asrc[ar + 8 * SA];
            float a2 = Asrc[ar + 4], a3 = Asrc[ar + 8 * SA + 4];
            ah[mt][0] = f2tf(a0); al[mt][0] = f2tf(a0 - __uint_as_float(ah[mt][0]));
            ah[mt][1] = f2tf(a1); al[mt][1] = f2tf(a1 - __uint_as_float(ah[mt][1]));
            ah[mt][2] = f2tf(a2); al[mt][2] = f2tf(a2 - __uint_as_float(ah[mt][2]));
            ah[mt][3] = f2tf(a3); al[mt][3] = f2tf(a3 - __uint_as_float(ah[mt][3]));
        }
#pragma unroll
        for (int nt = 0; nt < NT; nt++) {
            int ncol = warp_n * (NT * 8) + nt * 8 + (lane >> 2);
            int kr = (lane & 3) * SB;
            uint32_t bh[2], bl[2];
            bh[0] = sBh[kr + ncol]; bh[1] = sBh[kr + 4 * SB + ncol];
            bl[0] = sBl[kr + ncol]; bl[1] = sBl[kr + 4 * SB + ncol];
#pragma unroll
            for (int mt = 0; mt < 2; mt++) {
                mma_tf32(acc[mt][nt], ah[mt], bh);
                mma_tf32(acc[mt][nt], ah[mt], bl);
                mma_tf32(acc[mt][nt], al[mt], bh);
            }
        }
        __syncthreads();
    }
}

// ---------------- pre-pass batched GEMM: out = A(160000x128) @ W(128xNB) ----------------
template<int NT>
__global__ void __launch_bounds__(256, 2)
k_pre(const float* __restrict__ A, const uint32_t* __restrict__ BH,
      const uint32_t* __restrict__ BL, float* __restrict__ outp) {
    extern __shared__ float smem[];
    float* sA = smem;
    uint32_t* sBh = (uint32_t*)(smem + 64 * SA);
    uint32_t* sBl = sBh + 8 * 264;
    const int tid = threadIdx.x, lane = tid & 31, wid = tid >> 5;
    const int warp_m = wid & 1, warp_n = wid >> 1;
    const int row0 = blockIdx.x * 64;      // grid 2500, exact
    for (int i = tid; i < 64 * 32; i += 256) {
        int r = i >> 5, c4 = i & 31;
        *(float4*)&sA[r * SA + c4 * 4] = ((const float4*)A)[(size_t)(row0 + r) * 32 + c4];
    }
    __syncthreads();
    float acc[2][NT][4];
#pragma unroll
    for (int i = 0; i < 2; i++)
#pragma unroll
        for (int j = 0; j < NT; j++)
#pragma unroll
            for (int q = 0; q < 4; q++) acc[i][j][q] = 0.f;
    gemm_phase<NT, 128, 0>(sA, sA, sBh, sBl, BH, BL, tid, lane, warp_m, warp_n, acc);
#pragma unroll
    for (int mt = 0; mt < 2; mt++)
#pragma unroll
        for (int nt = 0; nt < NT; nt++) {
            int gcol = warp_n * (NT * 8) + nt * 8 + (lane & 3) * 2;
#pragma unroll
            for (int half = 0; half < 2; half++) {
                int grow = row0 + warp_m * 32 + mt * 16 + (lane >> 2) + half * 8;
                *(float2*)&outp[(size_t)grow * (NT * 32) + gcol] =
                    make_float2(acc[mt][nt][half * 2 + 0], acc[mt][nt][half * 2 + 1]);
            }
        }
}

// ---------------- fused cell: gate + candidate + blend ----------------
// PRE=1 (layer0): acc init from pre arrays, K=128 (hp half only), z kept in smem (sA).
//                 hin/hout are the double-buffered layer-0 states.
// PRE=0 (layer1): sA = agg (global), K=256, z via g_zg, hin==hout (in place).
template<int PRE, int WSEQ>
__global__ void __launch_bounds__(256, 2)
k_cell(const float* __restrict__ agg, const float* __restrict__ preZr,
       const float* __restrict__ preH,
       const float* __restrict__ hin, float* __restrict__ hout,
       const uint32_t* __restrict__ WzrH, const uint32_t* __restrict__ WzrL,
       const float* __restrict__ bzr,
       const uint32_t* __restrict__ WhH, const uint32_t* __restrict__ WhL,
       const float* __restrict__ bh, int t) {
    extern __shared__ float smem[];
    float* sA  = smem;                       // agg (PRE=0) | z-store (PRE=1)
    float* sA2 = smem + 64 * SA;             // hp -> r*hp
    uint32_t* sBh = (uint32_t*)(smem + 2 * 64 * SA);
    uint32_t* sBl = sBh + 8 * 264;
    const int tid = threadIdx.x, lane = tid & 31, wid = tid >> 5;
    const int warp_m = wid & 1, warp_n = wid >> 1;
    const int row0 = blockIdx.x * 64;

    // phase 0: load hp (and agg for PRE=0)
    for (int i = tid; i < 64 * 32; i += 256) {
        int r = i >> 5, c4 = i & 31;
        int grow = row0 + r;
        float4 v = (grow < NN) ? ((const float4*)hin)[grow * 32 + c4]
                               : make_float4(0.f, 0.f, 0.f, 0.f);
        *(float4*)&sA2[r * SA + c4 * 4] = v;
        if (!PRE) {
            float4 a = (grow < NN) ? ((const float4*)agg)[grow * 32 + c4]
                                   : make_float4(0.f, 0.f, 0.f, 0.f);
            *(float4*)&sA[r * SA + c4 * 4] = a;
        }
    }
    __syncthreads();

    // ---- gate (N=256) ----
    {
        float acc[2][8][4];
#pragma unroll
        for (int mt = 0; mt < 2; mt++)
#pragma unroll
            for (int nt = 0; nt < 8; nt++) {
                int gcol = warp_n * 64 + nt * 8 + (lane & 3) * 2;
#pragma unroll
                for (int half = 0; half < 2; half++) {
                    float2 v = make_float2(0.f, 0.f);
                    if (PRE) {
                        int grow = row0 + warp_m * 32 + mt * 16 + (lane >> 2) + half * 8;
                        if (grow < NN)
                            v = *(const float2*)&preZr[(size_t)grow * 256 + gcol];
                    }
                    acc[mt][nt][half * 2 + 0] = v.x;
                    acc[mt][nt][half * 2 + 1] = v.y;
                }
            }
        if (PRE)
            gemm_phase<8, 128, 128>(sA, sA2, sBh, sBl, WzrH, WzrL,
                                    tid, lane, warp_m, warp_n, acc);
        else
            gemm_phase<8, 256, 0>(sA, sA2, sBh, sBl, WzrH, WzrL,
                                  tid, lane, warp_m, warp_n, acc);
#pragma unroll
        for (int mt = 0; mt < 2; mt++)
#pragma unroll
            for (int nt = 0; nt < 8; nt++) {
                int gcol = warp_n * 64 + nt * 8 + (lane & 3) * 2;
                float b0 = bzr[gcol], b1 = bzr[gcol + 1];
#pragma unroll
                for (int half = 0; half < 2; half++) {
                    int lr = warp_m * 32 + mt * 16 + (lane >> 2) + half * 8;
                    int grow = row0 + lr;
                    float v0 = 1.f / (1.f + expf(-(acc[mt][nt][half * 2 + 0] + b0)));
                    float v1 = 1.f / (1.f + expf(-(acc[mt][nt][half * 2 + 1] + b1)));
                    if (gcol < 128) {
                        if (PRE)
                            *(float2*)&sA[lr * SA + gcol] = make_float2(v0, v1);
                        else if (grow < NN)
                            *(float2*)&g_zg[(size_t)grow * 128 + gcol] = make_float2(v0, v1);
                    } else {
                        int lc = gcol - 128;
                        float hp0 = sA2[lr * SA + lc];
                        float hp1 = sA2[lr * SA + lc + 1];
                        sA2[lr * SA + lc]     = v0 * hp0;
                        sA2[lr * SA + lc + 1] = v1 * hp1;
                    }
                }
            }
    }
    // (first __syncthreads inside next gemm_phase orders sA/sA2 writes before reads)

    // ---- candidate (N=128) + blend ----
    {
        float acc[2][4][4];
#pragma unroll
        for (int mt = 0; mt < 2; mt++)
#pragma unroll
            for (int nt = 0; nt < 4; nt++) {
                int gcol = warp_n * 32 + nt * 8 + (lane & 3) * 2;
#pragma unroll
                for (int half = 0; half < 2; half++) {
                    float2 v = make_float2(0.f, 0.f);
                    if (PRE) {
                        int grow = row0 + warp_m * 32 + mt * 16 + (lane >> 2) + half * 8;
                        if (grow < NN)
                            v = *(const float2*)&preH[(size_t)grow * 128 + gcol];
                    }
                    acc[mt][nt][half * 2 + 0] = v.x;
                    acc[mt][nt][half * 2 + 1] = v.y;
                }
            }
        if (PRE)
            gemm_phase<4, 128, 128>(sA, sA2, sBh, sBl, WhH, WhL,
                                    tid, lane, warp_m, warp_n, acc);
        else
            gemm_phase<4, 256, 0>(sA, sA2, sBh, sBl, WhH, WhL,
                                  tid, lane, warp_m, warp_n, acc);
#pragma unroll
        for (int mt = 0; mt < 2; mt++)
#pragma unroll
            for (int nt = 0; nt < 4; nt++) {
                int gcol = warp_n * 32 + nt * 8 + (lane & 3) * 2;
                float b0 = bh[gcol], b1 = bh[gcol + 1];
#pragma unroll
                for (int half = 0; half < 2; half++) {
                    int lr = warp_m * 32 + mt * 16 + (lane >> 2) + half * 8;
                    int grow = row0 + lr;
                    if (grow >= NN) continue;
                    size_t base = (size_t)grow * 128 + gcol;
                    float ht0 = tanhf(acc[mt][nt][half * 2 + 0] + b0);
                    float ht1 = tanhf(acc[mt][nt][half * 2 + 1] + b1);
                    float2 zv = PRE ? *(const float2*)&sA[lr * SA + gcol]
                                    : *(const float2*)&g_zg[base];
                    float2 hv = *(const float2*)&hin[base];
                    float hn0 = zv.x * hv.x + (1.f - zv.x) * ht0;
                    float hn1 = zv.y * hv.y + (1.f - zv.y) * ht1;
                    *(float2*)&hout[base] = make_float2(hn0, hn1);
                    if (WSEQ) {
                        size_t sb = (size_t)grow * (TT * HH) + t * HH + gcol;
                        *(float2*)&g_hseq[sb] = make_float2(hn0, hn1);
                    }
                }
            }
    }
}

// ---------------- temporal attention ----------------
__global__ void __launch_bounds__(128)
k_attn(const float* __restrict__ attW) {
    int n = blockIdx.x * blockDim.y + threadIdx.y;
    if (n >= NN) return;
    int lane = threadIdx.x;
    float4 aw = ((const float4*)attW)[lane];
    const float4* h4 = (const float4*)g_hseq + n * (TT * HH / 4) + lane;
    float4 hv[16];
    float s[16];
#pragma unroll
    for (int t = 0; t < TT; t++) {
        hv[t] = h4[t * 32];
        float d = hv[t].x * aw.x + hv[t].y * aw.y + hv[t].z * aw.z + hv[t].w * aw.w;
#pragma unroll
        for (int o = 16; o > 0; o >>= 1) d += __shfl_xor_sync(0xffffffffu, d, o);
        s[t] = d;
    }
    float m = s[0];
#pragma unroll
    for (int t = 1; t < TT; t++) m = fmaxf(m, s[t]);
    float sum = 0.f;
#pragma unroll
    for (int t = 0; t < TT; t++) { s[t] = expf(s[t] - m); sum += s[t]; }
    float inv = 1.f / sum;
    float4 c = make_float4(0.f, 0.f, 0.f, 0.f);
#pragma unroll
    for (int t = 0; t < TT; t++) {
        float w = s[t] * inv;
        c.x += w * hv[t].x; c.y += w * hv[t].y; c.z += w * hv[t].z; c.w += w * hv[t].w;
    }
    ((float4*)g_ctx)[n * 32 + lane] = c;
}

// ---------------- final projection (3xTF32, inline conversion) ----------------
__global__ void __launch_bounds__(256)
k_proj(const float* __restrict__ A1, const float* __restrict__ B,
       const float* __restrict__ bias, float* __restrict__ Cout, int M) {
    constexpr int SAp = 20;
    constexpr int SB = 72;
    __shared__ float sAh[128 * SAp];
    __shared__ float sAl[128 * SAp];
    __shared__ float sBh[16 * SB];
    __shared__ float sBl[16 * SB];
    const int tid = threadIdx.x, lane = tid & 31, wid = tid >> 5;
    const int warp_m = wid & 3, warp_n = wid >> 2;
    const int row0 = blockIdx.x * 128;
    const int col0 = blockIdx.y * 64;
    float acc[2][4][4];
#pragma unroll
    for (int i = 0; i < 2; i++)
#pragma unroll
        for (int j = 0; j < 4; j++)
#pragma unroll
            for (int q = 0; q < 4; q++) acc[i][j][q] = 0.f;

    for (int kt = 0; kt < 128; kt += 16) {
#pragma unroll
        for (int i = 0; i < 2; i++) {
            int lid = tid + i * 256;
            int m = lid >> 2, kq = (lid & 3) * 4;
            int grow = row0 + m;
            float4 a = (grow < M) ? *(const float4*)(A1 + (size_t)grow * 128 + kt + kq)
                                  : make_float4(0.f, 0.f, 0.f, 0.f);
            float4 h4, l4;
            h4.x = __uint_as_float(f2tf(a.x)); l4.x = __uint_as_float(f2tf(a.x - h4.x));
            h4.y = __uint_as_float(f2tf(a.y)); l4.y = __uint_as_float(f2tf(a.y - h4.y));
            h4.z = __uint_as_float(f2tf(a.z)); l4.z = __uint_as_float(f2tf(a.z - h4.z));
            h4.w = __uint_as_float(f2tf(a.w)); l4.w = __uint_as_float(f2tf(a.w - h4.w));
            *(float4*)&sAh[m * SAp + kq] = h4;
            *(float4*)&sAl[m * SAp + kq] = l4;
        }
        {
            int k = tid >> 4, nq = (tid & 15) * 4;
            float4 b = *(const float4*)&B[(size_t)(kt + k) * 128 + col0 + nq];
            float4 h4, l4;
            h4.x = __uint_as_float(f2tf(b.x)); l4.x = __uint_as_float(f2tf(b.x - h4.x));
            h4.y = __uint_as_float(f2tf(b.y)); l4.y = __uint_as_float(f2tf(b.y - h4.y));
            h4.z = __uint_as_float(f2tf(b.z)); l4.z = __uint_as_float(f2tf(b.z - h4.z));
            h4.w = __uint_as_float(f2tf(b.w)); l4.w = __uint_as_float(f2tf(b.w - h4.w));
            *(float4*)&sBh[k * SB + nq] = h4;
            *(float4*)&sBl[k * SB + nq] = l4;
        }
        __syncthreads();
#pragma unroll
        for (int k0 = 0; k0 < 16; k0 += 8) {
            uint32_t ah[2][4], al[2][4];
#pragma unroll
            for (int mt = 0; mt < 2; mt++) {
                int r0 = (warp_m * 32 + mt * 16 + (lane >> 2)) * SAp;
                int c0k = k0 + (lane & 3);
                ah[mt][0] = __float_as_uint(sAh[r0 + c0k]);
                ah[mt][1] = __float_as_uint(sAh[r0 + 8 * SAp + c0k]);
                ah[mt][2] = __float_as_uint(sAh[r0 + c0k + 4]);
                ah[mt][3] = __float_as_uint(sAh[r0 + 8 * SAp + c0k + 4]);
                al[mt][0] = __float_as_uint(sAl[r0 + c0k]);
                al[mt][1] = __float_as_uint(sAl[r0 + 8 * SAp + c0k]);
                al[mt][2] = __float_as_uint(sAl[r0 + c0k + 4]);
                al[mt][3] = __float_as_uint(sAl[r0 + 8 * SAp + c0k + 4]);
            }
#pragma unroll
            for (int nt = 0; nt < 4; nt++) {
                int ncol = warp_n * 32 + nt * 8 + (lane >> 2);
                int kr = (k0 + (lane & 3)) * SB;
                uint32_t bh[2], bl[2];
                bh[0] = __float_as_uint(sBh[kr + ncol]);
                bh[1] = __float_as_uint(sBh[kr + 4 * SB + ncol]);
                bl[0] = __float_as_uint(sBl[kr + ncol]);
                bl[1] = __float_as_uint(sBl[kr + 4 * SB + ncol]);
#pragma unroll
                for (int mt = 0; mt < 2; mt++) {
                    mma_tf32(acc[mt][nt], ah[mt], bh);
                    mma_tf32(acc[mt][nt], ah[mt], bl);
                    mma_tf32(acc[mt][nt], al[mt], bh);
                }
            }
        }
        __syncthreads();
    }
#pragma unroll
    for (int mt = 0; mt < 2; mt++)
#pragma unroll
        for (int nt = 0; nt < 4; nt++) {
            int gcol = col0 + warp_n * 32 + nt * 8 + (lane & 3) * 2;
            float b0 = bias[gcol], b1 = bias[gcol + 1];
#pragma unroll
            for (int half = 0; half < 2; half++) {
                int row = row0 + warp_m * 32 + mt * 16 + (lane >> 2) + half * 8;
                if (row >= M) continue;
                *(float2*)&Cout[(size_t)row * 128 + gcol] =
                    make_float2(acc[mt][nt][half * 2 + 0] + b0,
                                acc[mt][nt][half * 2 + 1] + b1);
            }
        }
}

// ---------------- launch ----------------

#define SMEM_CELL ((2 * 64 * SA) * 4 + 2 * 8 * 264 * 4)     // 84480
#define SMEM_PRE  ((64 * SA) * 4 + 2 * 8 * 264 * 4)         // 50688
#define SMEM_SCAN ((2 * NN + 1024) * 4)                     // 84096

extern "C" void kernel_launch(void* const* d_in, const int* in_sizes, int n_in,
                              void* d_out, int out_size) {
    const float* x   = (const float*)d_in[0];
    const int*   ei  = (const int*)d_in[1];
    const float* ew  = (const float*)d_in[2];
    WPtrs P;
    P.Wc[0] = (const float*)d_in[3];  P.bc[0] = (const float*)d_in[4];
    P.Wl[0] = (const float*)d_in[5];  P.bl[0] = (const float*)d_in[6];
    P.Wc[1] = (const float*)d_in[7];  P.bc[1] = (const float*)d_in[8];
    P.Wl[1] = (const float*)d_in[9];  P.bl[1] = (const float*)d_in[10];
    P.Wc[2] = (const float*)d_in[11]; P.bc[2] = (const float*)d_in[12];
    P.Wl[2] = (const float*)d_in[13]; P.bl[2] = (const float*)d_in[14];
    const float* attW = (const float*)d_in[15];
    const float* outW = (const float*)d_in[17];
    const float* outb = (const float*)d_in[18];
    float* out = (float*)d_out;

    float *p_xT, *p_h0, *p_h1, *p_agg, *p_agg0, *p_preZr, *p_preH, *p_ctx, *p_bzr, *p_bh;
    uint32_t *p_WzrH, *p_WzrL, *p_WhH, *p_WhL;
    cudaGetSymbolAddress((void**)&p_xT,    g_xT);
    cudaGetSymbolAddress((void**)&p_h0,    g_h0);
    cudaGetSymbolAddress((void**)&p_h1,    g_h1);
    cudaGetSymbolAddress((void**)&p_agg,   g_agg);
    cudaGetSymbolAddress((void**)&p_agg0,  g_agg0);
    cudaGetSymbolAddress((void**)&p_preZr, g_pre_zr);
    cudaGetSymbolAddress((void**)&p_preH,  g_pre_h);
    cudaGetSymbolAddress((void**)&p_ctx,   g_ctx);
    cudaGetSymbolAddress((void**)&p_WzrH,  g_WzrH);
    cudaGetSymbolAddress((void**)&p_WzrL,  g_WzrL);
    cudaGetSymbolAddress((void**)&p_WhH,   g_WhH);
    cudaGetSymbolAddress((void**)&p_WhL,   g_WhL);
    cudaGetSymbolAddress((void**)&p_bzr,   g_bzr);
    cudaGetSymbolAddress((void**)&p_bh,    g_bh);

    cudaFuncSetAttribute(k_cell<1,0>, cudaFuncAttributeMaxDynamicSharedMemorySize, SMEM_CELL);
    cudaFuncSetAttribute(k_cell<0,1>, cudaFuncAttributeMaxDynamicSharedMemorySize, SMEM_CELL);
    cudaFuncSetAttribute(k_pre<8>,   cudaFuncAttributeMaxDynamicSharedMemorySize, SMEM_PRE);
    cudaFuncSetAttribute(k_pre<4>,   cudaFuncAttributeMaxDynamicSharedMemorySize, SMEM_PRE);
    cudaFuncSetAttribute(k_scan2,    cudaFuncAttributeMaxDynamicSharedMemorySize, SMEM_SCAN);

    const int GC = (NN + 63) / 64;                  // 157
    const int GX = (NN + 127) / 128;                // 79

    // Fork stream + events. Created fresh each call (kernel_launch runs only for
    // correctness + capture, never on replay) and intentionally NOT destroyed:
    // destroying a stream/event participating in an active capture invalidates it.
    cudaStream_t sL0;
    cudaStreamCreateWithFlags(&sL0, cudaStreamNonBlocking);
    cudaEvent_t evRoot, evA[TT], evS[TT];
    cudaEventCreateWithFlags(&evRoot, cudaEventDisableTiming);
    for (int t = 0; t < TT; t++) {
        cudaEventCreateWithFlags(&evA[t], cudaEventDisableTiming);
        cudaEventCreateWithFlags(&evS[t], cudaEventDisableTiming);
    }

    // ---- prepass (capture stream) ----
    k_boot<<<5768, 256>>>(x, P);
    k_scan2<<<1, 1024, SMEM_SCAN>>>(ei, ew);
    k_scatter<<<(EE + 255) / 256, 256>>>(ei, ew);
    k_spmm<<<dim3(1250, 16), dim3(32, 8)>>>(p_xT, p_agg0);                 // all-t layer-0 agg
    k_pre<8><<<2500, 256, SMEM_PRE>>>(p_agg0, p_WzrH, p_WzrL, p_preZr);    // agg0 @ W1zr
    k_pre<4><<<2500, 256, SMEM_PRE>>>(p_agg0, p_WhH, p_WhL, p_preH);       // agg0 @ W1h

    cudaEventRecord(evRoot, 0);
    cudaStreamWaitEvent(sL0, evRoot, 0);

    // ---- pipelined recurrence ----
    // Chain A (sL0):   cell1(t): h0buf[t&1] -> h0buf[(t+1)&1]
    // Chain B (capture stream): spmm(t) reads h0buf[(t+1)&1] -> agg; cell0(t): h1 in place.
    // WAR: cell1(t) overwrites h0buf[(t+1)&1], read by spmm(t-2) -> wait evS[t-2].
    for (int t = 0; t < TT; t++) {
        if (t >= 2) cudaStreamWaitEvent(sL0, evS[t - 2], 0);
        k_cell<1,0><<<GC, 256, SMEM_CELL, sL0>>>(nullptr,
            p_preZr + (size_t)t * NN * 256, p_preH + (size_t)t * NN * 128,
            p_h0 + (size_t)(t & 1) * NN * HH, p_h0 + (size_t)((t + 1) & 1) * NN * HH,
            p_WzrH + 128 * 256, p_WzrL + 128 * 256, p_bzr,
            p_WhH + 128 * 128, p_WhL + 128 * 128, p_bh, t);
        cudaEventRecord(evA[t], sL0);

        cudaStreamWaitEvent(0, evA[t], 0);
        k_spmm<<<dim3(1250, 1), dim3(32, 8)>>>(p_h0 + (size_t)((t + 1) & 1) * NN * HH, p_agg);
        cudaEventRecord(evS[t], 0);
        k_cell<0,1><<<GC, 256, SMEM_CELL>>>(p_agg, nullptr, nullptr, p_h1, p_h1,
            p_WzrH + 256 * 256, p_WzrL + 256 * 256, p_bzr + 256,
            p_WhH + 256 * 128, p_WhL + 256 * 128, p_bh + 128, t);
    }
    // Join: capture stream already waited on evA[15] (before spmm(15)); chain A has
    // no work after that record, so the fork is fully joined.

    k_attn<<<(NN + 3) / 4, dim3(32, 4)>>>(attW);
    k_proj<<<dim3(GX, 2), 256>>>(p_ctx, outW, outb, out, NN);
}